// round 7
// baseline (speedup 1.0000x reference)
#include <cuda_runtime.h>
#include <math.h>

// Problem constants (fixed by setup_inputs)
#define Bc   4
#define Ec   16
#define Cc   24
#define HWc  262144            // 512*512
#define TILE 1024              // pixels per pass-1 block (1024 blocks total)

#define DELTA_VAR  0.75f
#define DELTA_DIST 2.0f
#define ALPHA_W 1.0f
#define BETA_W  1.0f
#define GAMMA_W 0.001f

#define VAR_GRID_X 256         // k_var blocks per batch (1024 pixels each)
#define VAR_BLOCKS (VAR_GRID_X * Bc)   // 1024 blocks: small CTAs, self-balancing

// ---------------- device scratch (no allocation allowed) ----------------
// Zero at module load; the elected last k_var block re-zeroes after use, so
// every graph replay sees identical initial state.
__device__ float g_sum[Bc * Cc * Ec];   // [b][c][e] cluster embedding sums
__device__ float g_cnt[Bc * Cc];        // [b][c]    pixel counts
__device__ unsigned int g_ticket;       // last-block election for reset

// ---------------- kernel 1: per-(b,c) sums + counts ----------------
// Block = 256 threads as 16(e) x 16(j). Thread (e,j) privately owns shared
// column e*16+j of acc[C][E][16] -> bank == lane, conflict-free RMW, no
// atomics in the hot loop. Labels staged once per tile, reused for all 16 e.
// TILE=1024 -> 1024 blocks (~7 CTAs/SM, smem-limited 8): grid no longer the
// occupancy cap.
__global__ void __launch_bounds__(256)
k_sums(const float* __restrict__ input, const int* __restrict__ target,
       float* __restrict__ out) {
    __shared__ float  acc[Cc * 256];     // [c][e*16+j]  24 KB
    __shared__ uchar4 lab4[TILE / 4];    // 1 KB of labels (values 0..23)
    __shared__ int    hist[Cc];

    const int tid   = threadIdx.x;
    const int b     = blockIdx.y;
    const int tile0 = blockIdx.x * TILE;

    // initialize the output accumulator for this invocation (out is poisoned)
    if (blockIdx.x == 0 && blockIdx.y == 0 && tid == 0) out[0] = 0.f;

    #pragma unroll
    for (int i = tid; i < Cc * 256; i += 256) acc[i] = 0.f;
    if (tid < Cc) hist[tid] = 0;
    __syncthreads();

    // stage labels (coalesced int4 loads) + histogram (few shared atomics)
    const int4* tgt4 = (const int4*)(target + b * HWc + tile0);
    if (tid < TILE / 4) {
        int4 l = tgt4[tid];
        lab4[tid] = make_uchar4((unsigned char)l.x, (unsigned char)l.y,
                                (unsigned char)l.z, (unsigned char)l.w);
        atomicAdd(&hist[l.x], 1); atomicAdd(&hist[l.y], 1);
        atomicAdd(&hist[l.z], 1); atomicAdd(&hist[l.w], 1);
    }
    __syncthreads();

    const int e = tid >> 4;
    const int j = tid & 15;
    const float4* src =
        (const float4*)(input + (size_t)b * Ec * HWc + (size_t)e * HWc + tile0);
    float* accej = acc + e * 16 + j;     // column base; index lbl*256

    #pragma unroll
    for (int k = 0; k < TILE / 64; ++k) {
        float4 v = src[k * 16 + j];              // pixels k*64 + j*4 .. +3
        uchar4 l = lab4[k * 16 + j];
        accej[(int)l.x * 256] += v.x;
        accej[(int)l.y * 256] += v.y;
        accej[(int)l.z * 256] += v.z;
        accej[(int)l.w * 256] += v.w;
    }
    __syncthreads();

    // reduce over j (16 columns) once per block, then global accumulate
    for (int o = tid; o < Cc * Ec; o += 256) {   // o = c*16 + e
        float s = 0.f;
        #pragma unroll
        for (int jj = 0; jj < 16; ++jj) s += acc[o * 16 + jj];
        atomicAdd(&g_sum[b * Cc * Ec + o], s);
    }
    if (tid < Cc) atomicAdd(&g_cnt[b * Cc + tid], (float)hist[tid]);
}

// ---------------- kernel 2: hinged variance (+ dist/reg in one block) ------
// 1024 small blocks (self-balancing). Loads run in EIGHT waves of 2 LDG.128
// so live regs fit 8 CTAs/SM (__launch_bounds__(256,8) -> occ ~90-100%).
// In-flight bytes/SM (8*256*2*16B = 64KB) still exceeds the L2 BW*latency
// product (~10KB/SM), so MLP is not the constraint — raising issue slots is
// pure win in the L2-resident timed regime. Per-block result -> single
// atomicAdd(out); block (0,0) adds distance/reg terms; ticket-elected last
// block resets scratch.
__global__ void __launch_bounds__(256, 8)
k_var(const float* __restrict__ input, const int* __restrict__ target,
      float* __restrict__ out) {
    __shared__ float mu_t[Ec * Cc];        // transposed [e][c]
    __shared__ float rc[Cc];               // 1 / (cnt * B * C)
    __shared__ float mu_all[Bc * Cc * Ec]; // [b][c][e] (block (0,0) only)
    __shared__ float red[8];

    const int tid = threadIdx.x;
    const int b   = blockIdx.y;
    const bool block00 = (blockIdx.x == 0 && blockIdx.y == 0);

    const int p4 = (blockIdx.x * 256 + tid) * 4;
    const int4 l = *(const int4*)(target + b * HWc + p4);
    const float* base = input + (size_t)b * Ec * HWc + p4;

    // ---- means for this batch into shared ----
    for (int i = tid; i < Cc * Ec; i += 256) {   // i = c*16 + e
        int c = i >> 4, e = i & 15;
        mu_t[e * Cc + c] = g_sum[b * Cc * Ec + i] / g_cnt[b * Cc + c];
    }
    if (tid < Cc)
        rc[tid] = 1.0f / (g_cnt[b * Cc + tid] * (float)(Bc * Cc));
    __syncthreads();

    float s0 = 0.f, s1 = 0.f, s2 = 0.f, s3 = 0.f;

    // ---- eight waves of 2 LDG.128: batch-load, then consume ----
    #pragma unroll
    for (int w = 0; w < 8; ++w) {
        float4 v0 = *(const float4*)(base + (size_t)(w * 2 + 0) * HWc);
        float4 v1 = *(const float4*)(base + (size_t)(w * 2 + 1) * HWc);
        const float* m0 = mu_t + (w * 2 + 0) * Cc;
        const float* m1 = mu_t + (w * 2 + 1) * Cc;
        float d0, d1, d2, d3;
        d0 = v0.x - m0[l.x]; s0 += d0 * d0;
        d1 = v0.y - m0[l.y]; s1 += d1 * d1;
        d2 = v0.z - m0[l.z]; s2 += d2 * d2;
        d3 = v0.w - m0[l.w]; s3 += d3 * d3;
        d0 = v1.x - m1[l.x]; s0 += d0 * d0;
        d1 = v1.y - m1[l.y]; s1 += d1 * d1;
        d2 = v1.z - m1[l.z]; s2 += d2 * d2;
        d3 = v1.w - m1[l.w]; s3 += d3 * d3;
    }

    float h0 = fmaxf(sqrtf(s0) - DELTA_VAR, 0.f);
    float h1 = fmaxf(sqrtf(s1) - DELTA_VAR, 0.f);
    float h2 = fmaxf(sqrtf(s2) - DELTA_VAR, 0.f);
    float h3 = fmaxf(sqrtf(s3) - DELTA_VAR, 0.f);

    float acc = ALPHA_W * (h0 * h0 * rc[l.x] + h1 * h1 * rc[l.y] +
                           h2 * h2 * rc[l.z] + h3 * h3 * rc[l.w]);

    // ---- block (0,0): distance + regularizer terms over all batches ----
    if (block00) {
        for (int i = tid; i < Bc * Cc * Ec; i += 256) {
            int bc = i >> 4;
            mu_all[i] = g_sum[i] / g_cnt[bc];
        }
        __syncthreads();

        // reg term: one entry per (b,c)
        for (int i = tid; i < Bc * Cc; i += 256) {
            float nsq = 0.f;
            #pragma unroll
            for (int e = 0; e < Ec; ++e) {
                float m = mu_all[i * 16 + e]; nsq += m * m;
            }
            float regc = (nsq == 0.f) ? 0.f : sqrtf(nsq);
            acc += GAMMA_W * regc * (1.0f / (Cc * Bc));
        }
        // distance term: all ordered pairs (ci != cj)
        for (int t = tid; t < Bc * Cc * Cc; t += 256) {
            int bb = t / (Cc * Cc);
            int rcidx = t - bb * (Cc * Cc);
            int ci = rcidx / Cc, cj = rcidx - ci * Cc;
            if (ci != cj) {
                const float* a = mu_all + (bb * Cc + ci) * 16;
                const float* c = mu_all + (bb * Cc + cj) * 16;
                float s = 0.f;
                #pragma unroll
                for (int e = 0; e < Ec; ++e) { float d = a[e] - c[e]; s += d * d; }
                float dist = (s == 0.f) ? 0.f : sqrtf(s);
                float hd = fmaxf(2.0f * DELTA_DIST - dist, 0.f);
                acc += BETA_W * hd * hd * (1.0f / ((float)Bc * Cc * (Cc - 1)));
            }
        }
    }

    // ---- block reduction -> single global atomic ----
    #pragma unroll
    for (int o = 16; o > 0; o >>= 1)
        acc += __shfl_down_sync(0xffffffffu, acc, o);
    if ((tid & 31) == 0) red[tid >> 5] = acc;
    __syncthreads();
    if (tid == 0) {
        float s = red[0];
        #pragma unroll
        for (int w = 1; w < 8; ++w) s += red[w];
        atomicAdd(out, s);
    }

    // ---- last-block election: reset scratch for next replay ----
    __syncthreads();
    __shared__ unsigned int s_last;
    if (tid == 0)
        s_last = (atomicAdd(&g_ticket, 1u) == (unsigned)(VAR_BLOCKS - 1));
    __syncthreads();
    if (s_last) {
        for (int i = tid; i < Bc * Cc * Ec; i += 256) g_sum[i] = 0.f;
        if (tid < Bc * Cc) g_cnt[tid] = 0.f;
        if (tid == 0) g_ticket = 0u;
    }
}

// ---------------- launch ----------------
extern "C" void kernel_launch(void* const* d_in, const int* in_sizes, int n_in,
                              void* d_out, int out_size) {
    const float* input  = (const float*)d_in[0];
    const int*   target = (const int*)d_in[1];
    float*       out    = (float*)d_out;

    dim3 g1(HWc / TILE, Bc);           // 256 x 4 = 1024 blocks
    k_sums<<<g1, 256>>>(input, target, out);

    dim3 g2(VAR_GRID_X, Bc);           // 256 x 4 = 1024 blocks
    k_var<<<g2, 256>>>(input, target, out);
}

// round 8
// speedup vs baseline: 1.0816x; 1.0816x over previous
#include <cuda_runtime.h>
#include <math.h>

// Problem constants (fixed by setup_inputs)
#define Bc   4
#define Ec   16
#define Cc   24
#define HWc  262144            // 512*512
#define TILE 2048              // pixels per pass-1 block (512 blocks: R6 optimum)

#define DELTA_VAR  0.75f
#define DELTA_DIST 2.0f
#define ALPHA_W 1.0f
#define BETA_W  1.0f
#define GAMMA_W 0.001f

#define VAR_GRID_X 256         // k_var blocks per batch (1024 pixels each)
#define VAR_BLOCKS (VAR_GRID_X * Bc)   // 1024 small blocks: self-balancing

// ---------------- device scratch (no allocation allowed) ----------------
__device__ float g_sum[Bc * Cc * Ec];     // [b][c][e] cluster embedding sums
__device__ float g_cnt[Bc * Cc];          // [b][c]    pixel counts
__device__ uchar4 g_lab[Bc * HWc / 4];    // compacted labels (rewritten each run)
__device__ unsigned int g_ticket;         // last-block election for reset

// ---------------- kernel 1: per-(b,c) sums + counts ----------------
// Block = 256 threads as 16(e) x 16(j). Thread (e,j) privately owns shared
// column e*16+j of acc[C][E][16] -> bank == lane, conflict-free RMW, no
// atomics in the hot loop. Labels staged once per tile, reused for all 16 e,
// and spilled compacted (uchar4) to global so k_var reads 1MB instead of 4MB.
__global__ void __launch_bounds__(256)
k_sums(const float* __restrict__ input, const int* __restrict__ target,
       float* __restrict__ out) {
    __shared__ float  acc[Cc * 256];     // [c][e*16+j]  24 KB
    __shared__ uchar4 lab4[TILE / 4];    // 2 KB of labels (values 0..23)
    __shared__ int    hist[Cc];

    const int tid   = threadIdx.x;
    const int b     = blockIdx.y;
    const int tile0 = blockIdx.x * TILE;

    // initialize the output accumulator for this invocation (out is poisoned)
    if (blockIdx.x == 0 && blockIdx.y == 0 && tid == 0) out[0] = 0.f;

    #pragma unroll
    for (int i = tid; i < Cc * 256; i += 256) acc[i] = 0.f;
    if (tid < Cc) hist[tid] = 0;
    __syncthreads();

    // stage labels (coalesced int4 loads) + histogram + compacted global copy
    const int4* tgt4 = (const int4*)(target + b * HWc + tile0);
    #pragma unroll
    for (int i = tid; i < TILE / 4; i += 256) {
        int4 l = tgt4[i];
        uchar4 u = make_uchar4((unsigned char)l.x, (unsigned char)l.y,
                               (unsigned char)l.z, (unsigned char)l.w);
        lab4[i] = u;
        g_lab[(size_t)b * (HWc / 4) + tile0 / 4 + i] = u;
        atomicAdd(&hist[l.x], 1); atomicAdd(&hist[l.y], 1);
        atomicAdd(&hist[l.z], 1); atomicAdd(&hist[l.w], 1);
    }
    __syncthreads();

    const int e = tid >> 4;
    const int j = tid & 15;
    const float4* src =
        (const float4*)(input + (size_t)b * Ec * HWc + (size_t)e * HWc + tile0);
    float* accej = acc + e * 16 + j;     // column base; index lbl*256

    #pragma unroll 8
    for (int k = 0; k < TILE / 64; ++k) {
        float4 v = src[k * 16 + j];              // pixels k*64 + j*4 .. +3
        uchar4 l = lab4[k * 16 + j];
        accej[(int)l.x * 256] += v.x;
        accej[(int)l.y * 256] += v.y;
        accej[(int)l.z * 256] += v.z;
        accej[(int)l.w * 256] += v.w;
    }
    __syncthreads();

    // reduce over j (16 columns) once per block, then global accumulate
    for (int o = tid; o < Cc * Ec; o += 256) {   // o = c*16 + e
        float s = 0.f;
        #pragma unroll
        for (int jj = 0; jj < 16; ++jj) s += acc[o * 16 + jj];
        atomicAdd(&g_sum[b * Cc * Ec + o], s);
    }
    if (tid < Cc) atomicAdd(&g_cnt[b * Cc + tid], (float)hist[tid]);
}

// ---------------- kernel 2: hinged variance (+ dist/reg in one block) ------
// R6 champion config: 1024 small blocks, four waves of 4 LDG.128, 6 CTAs/SM.
// Distance decomposition ||x-mu||^2 = ||x||^2 - 2 x.mu + ||mu||^2 splits the
// math into an LDS-independent FMA chain (||x||^2) that issues during gather
// latency, plus the x.mu gather chain. Labels come from the 1MB compacted
// cache. Per-block result -> single atomicAdd(out); block (0,0) adds the
// distance/reg terms; ticket-elected last block resets scratch.
__global__ void __launch_bounds__(256, 6)
k_var(const float* __restrict__ input, float* __restrict__ out) {
    __shared__ float mu_t[Ec * Cc];        // transposed [e][c]
    __shared__ float mnorm[Cc];            // ||mu_c||^2
    __shared__ float rc[Cc];               // 1 / (cnt * B * C)
    __shared__ float mu_all[Bc * Cc * Ec]; // [b][c][e] (block (0,0) only)
    __shared__ float red[8];

    const int tid = threadIdx.x;
    const int b   = blockIdx.y;
    const bool block00 = (blockIdx.x == 0 && blockIdx.y == 0);

    const int pq = blockIdx.x * 256 + tid;           // pixel-quad index
    const uchar4 l = g_lab[(size_t)b * (HWc / 4) + pq];
    const float* base = input + (size_t)b * Ec * HWc + pq * 4;

    // ---- means for this batch into shared ----
    for (int i = tid; i < Cc * Ec; i += 256) {   // i = c*16 + e
        int c = i >> 4, e = i & 15;
        mu_t[e * Cc + c] = g_sum[b * Cc * Ec + i] / g_cnt[b * Cc + c];
    }
    if (tid < Cc)
        rc[tid] = 1.0f / (g_cnt[b * Cc + tid] * (float)(Bc * Cc));
    __syncthreads();
    if (tid < Cc) {
        float nsq = 0.f;
        #pragma unroll
        for (int e = 0; e < Ec; ++e) {
            float m = mu_t[e * Cc + tid]; nsq += m * m;
        }
        mnorm[tid] = nsq;
    }
    __syncthreads();

    // x-norm chains (LDS-independent) and x.mu chains (LDS-dependent)
    float n0 = 0.f, n1 = 0.f, n2 = 0.f, n3 = 0.f;
    float p0 = 0.f, p1 = 0.f, p2 = 0.f, p3 = 0.f;

    // ---- four waves of 4 LDG.128: batch-load, then consume ----
    #pragma unroll
    for (int w = 0; w < 4; ++w) {
        float4 v[4];
        #pragma unroll
        for (int e = 0; e < 4; ++e)
            v[e] = *(const float4*)(base + (size_t)(w * 4 + e) * HWc);
        #pragma unroll
        for (int e = 0; e < 4; ++e) {
            const float* m = mu_t + (w * 4 + e) * Cc;
            n0 += v[e].x * v[e].x;  p0 += v[e].x * m[l.x];
            n1 += v[e].y * v[e].y;  p1 += v[e].y * m[l.y];
            n2 += v[e].z * v[e].z;  p2 += v[e].z * m[l.z];
            n3 += v[e].w * v[e].w;  p3 += v[e].w * m[l.w];
        }
    }

    float s0 = fmaxf(n0 - 2.f * p0 + mnorm[l.x], 0.f);
    float s1 = fmaxf(n1 - 2.f * p1 + mnorm[l.y], 0.f);
    float s2 = fmaxf(n2 - 2.f * p2 + mnorm[l.z], 0.f);
    float s3 = fmaxf(n3 - 2.f * p3 + mnorm[l.w], 0.f);

    float h0 = fmaxf(sqrtf(s0) - DELTA_VAR, 0.f);
    float h1 = fmaxf(sqrtf(s1) - DELTA_VAR, 0.f);
    float h2 = fmaxf(sqrtf(s2) - DELTA_VAR, 0.f);
    float h3 = fmaxf(sqrtf(s3) - DELTA_VAR, 0.f);

    float acc = ALPHA_W * (h0 * h0 * rc[l.x] + h1 * h1 * rc[l.y] +
                           h2 * h2 * rc[l.z] + h3 * h3 * rc[l.w]);

    // ---- block (0,0): distance + regularizer terms over all batches ----
    if (block00) {
        for (int i = tid; i < Bc * Cc * Ec; i += 256) {
            int bc = i >> 4;
            mu_all[i] = g_sum[i] / g_cnt[bc];
        }
        __syncthreads();

        // reg term: one entry per (b,c)
        for (int i = tid; i < Bc * Cc; i += 256) {
            float nsq = 0.f;
            #pragma unroll
            for (int e = 0; e < Ec; ++e) {
                float m = mu_all[i * 16 + e]; nsq += m * m;
            }
            float regc = (nsq == 0.f) ? 0.f : sqrtf(nsq);
            acc += GAMMA_W * regc * (1.0f / (Cc * Bc));
        }
        // distance term: all ordered pairs (ci != cj)
        for (int t = tid; t < Bc * Cc * Cc; t += 256) {
            int bb = t / (Cc * Cc);
            int rcidx = t - bb * (Cc * Cc);
            int ci = rcidx / Cc, cj = rcidx - ci * Cc;
            if (ci != cj) {
                const float* a = mu_all + (bb * Cc + ci) * 16;
                const float* c = mu_all + (bb * Cc + cj) * 16;
                float s = 0.f;
                #pragma unroll
                for (int e = 0; e < Ec; ++e) { float d = a[e] - c[e]; s += d * d; }
                float dist = (s == 0.f) ? 0.f : sqrtf(s);
                float hd = fmaxf(2.0f * DELTA_DIST - dist, 0.f);
                acc += BETA_W * hd * hd * (1.0f / ((float)Bc * Cc * (Cc - 1)));
            }
        }
    }

    // ---- block reduction -> single global atomic ----
    #pragma unroll
    for (int o = 16; o > 0; o >>= 1)
        acc += __shfl_down_sync(0xffffffffu, acc, o);
    if ((tid & 31) == 0) red[tid >> 5] = acc;
    __syncthreads();
    if (tid == 0) {
        float s = red[0];
        #pragma unroll
        for (int w = 1; w < 8; ++w) s += red[w];
        atomicAdd(out, s);
    }

    // ---- last-block election: reset scratch for next replay ----
    __syncthreads();
    __shared__ unsigned int s_last;
    if (tid == 0)
        s_last = (atomicAdd(&g_ticket, 1u) == (unsigned)(VAR_BLOCKS - 1));
    __syncthreads();
    if (s_last) {
        for (int i = tid; i < Bc * Cc * Ec; i += 256) g_sum[i] = 0.f;
        if (tid < Bc * Cc) g_cnt[tid] = 0.f;
        if (tid == 0) g_ticket = 0u;
    }
}

// ---------------- launch ----------------
extern "C" void kernel_launch(void* const* d_in, const int* in_sizes, int n_in,
                              void* d_out, int out_size) {
    const float* input  = (const float*)d_in[0];
    const int*   target = (const int*)d_in[1];
    float*       out    = (float*)d_out;

    dim3 g1(HWc / TILE, Bc);           // 128 x 4 = 512 blocks (R6 optimum)
    k_sums<<<g1, 256>>>(input, target, out);

    dim3 g2(VAR_GRID_X, Bc);           // 256 x 4 = 1024 blocks
    k_var<<<g2, 256>>>(input, out);
}

// round 9
// speedup vs baseline: 1.0830x; 1.0013x over previous
#include <cuda_runtime.h>
#include <math.h>

// Problem constants (fixed by setup_inputs)
#define Bc   4
#define Ec   16
#define Cc   24
#define HWc  262144            // 512*512
#define TILE 2048              // pixels per pass-1 block (512 blocks: optimum)

#define DELTA_VAR  0.75f
#define DELTA_DIST 2.0f
#define ALPHA_W 1.0f
#define BETA_W  1.0f
#define GAMMA_W 0.001f

#define VAR_GRID_X 256         // k_var blocks per batch (1024 pixels each)
#define VAR_BLOCKS (VAR_GRID_X * Bc)   // 1024 small blocks: self-balancing

// ---------------- device scratch (no allocation allowed) ----------------
__device__ float g_sum[Bc * Cc * Ec];     // [b][c][e] cluster embedding sums
__device__ float g_cnt[Bc * Cc];          // [b][c]    pixel counts
__device__ unsigned int g_ticket;         // last-block election for reset

// ---------------- kernel 1: per-(b,c) sums + counts ----------------
// Block = 256 threads as 16(e) x 16(j). Thread (e,j) privately owns shared
// column e*16+j of acc[C][E][16] -> bank == lane, conflict-free RMW, no
// atomics in the hot loop. Labels staged once per tile, reused for all 16 e.
// Triggers programmatic launch of k_var immediately: k_var's pre-sync part
// reads only the raw inputs, so it can overlap with this kernel entirely.
__global__ void __launch_bounds__(256)
k_sums(const float* __restrict__ input, const int* __restrict__ target,
       float* __restrict__ out) {
    __shared__ float  acc[Cc * 256];     // [c][e*16+j]  24 KB
    __shared__ uchar4 lab4[TILE / 4];    // 2 KB of labels (values 0..23)
    __shared__ int    hist[Cc];

    const int tid   = threadIdx.x;
    const int b     = blockIdx.y;
    const int tile0 = blockIdx.x * TILE;

    // let the dependent k_var grid start early (PDL)
    cudaTriggerProgrammaticLaunchCompletion();

    // initialize the output accumulator for this invocation (out is poisoned)
    if (blockIdx.x == 0 && blockIdx.y == 0 && tid == 0) out[0] = 0.f;

    #pragma unroll
    for (int i = tid; i < Cc * 256; i += 256) acc[i] = 0.f;
    if (tid < Cc) hist[tid] = 0;
    __syncthreads();

    // stage labels (coalesced int4 loads) + histogram (few shared atomics)
    const int4* tgt4 = (const int4*)(target + b * HWc + tile0);
    #pragma unroll
    for (int i = tid; i < TILE / 4; i += 256) {
        int4 l = tgt4[i];
        lab4[i] = make_uchar4((unsigned char)l.x, (unsigned char)l.y,
                              (unsigned char)l.z, (unsigned char)l.w);
        atomicAdd(&hist[l.x], 1); atomicAdd(&hist[l.y], 1);
        atomicAdd(&hist[l.z], 1); atomicAdd(&hist[l.w], 1);
    }
    __syncthreads();

    const int e = tid >> 4;
    const int j = tid & 15;
    const float4* src =
        (const float4*)(input + (size_t)b * Ec * HWc + (size_t)e * HWc + tile0);
    float* accej = acc + e * 16 + j;     // column base; index lbl*256

    #pragma unroll 8
    for (int k = 0; k < TILE / 64; ++k) {
        float4 v = src[k * 16 + j];              // pixels k*64 + j*4 .. +3
        uchar4 l = lab4[k * 16 + j];
        accej[(int)l.x * 256] += v.x;
        accej[(int)l.y * 256] += v.y;
        accej[(int)l.z * 256] += v.z;
        accej[(int)l.w * 256] += v.w;
    }
    __syncthreads();

    // reduce over j (16 columns) once per block, then global accumulate
    for (int o = tid; o < Cc * Ec; o += 256) {   // o = c*16 + e
        float s = 0.f;
        #pragma unroll
        for (int jj = 0; jj < 16; ++jj) s += acc[o * 16 + jj];
        atomicAdd(&g_sum[b * Cc * Ec + o], s);
    }
    if (tid < Cc) atomicAdd(&g_cnt[b * Cc + tid], (float)hist[tid]);
}

// ---------------- kernel 2: hinged variance (+ dist/reg in one block) ------
// PDL consumer. Pre-sync: label load + wave-0 input loads (inputs only — no
// dependence on k_sums). cudaGridDependencySynchronize() before touching
// g_sum/g_cnt. Then the proven R6 body: four waves of 4 LDG.128, 6 CTAs/SM,
// n/p ILP decomposition. Per-block result -> single atomicAdd(out); block
// (0,0) adds distance/reg terms; ticket-elected last block resets scratch.
__global__ void __launch_bounds__(256, 6)
k_var(const float* __restrict__ input, const int* __restrict__ target,
      float* __restrict__ out) {
    __shared__ float mu_t[Ec * Cc];        // transposed [e][c]
    __shared__ float mnorm[Cc];            // ||mu_c||^2
    __shared__ float rc[Cc];               // 1 / (cnt * B * C)
    __shared__ float mu_all[Bc * Cc * Ec]; // [b][c][e] (block (0,0) only)
    __shared__ float red[8];

    const int tid = threadIdx.x;
    const int b   = blockIdx.y;
    const bool block00 = (blockIdx.x == 0 && blockIdx.y == 0);

    const int pq = blockIdx.x * 256 + tid;           // pixel-quad index
    const int4 l = *(const int4*)(target + b * HWc + pq * 4);
    const float* base = input + (size_t)b * Ec * HWc + pq * 4;

    // pre-sync prefetch: wave 0 of input (independent of k_sums results)
    float4 v0[4];
    #pragma unroll
    for (int e = 0; e < 4; ++e)
        v0[e] = *(const float4*)(base + (size_t)e * HWc);

    // wait for k_sums' g_sum/g_cnt to be complete and visible
    cudaGridDependencySynchronize();

    // ---- means for this batch into shared ----
    for (int i = tid; i < Cc * Ec; i += 256) {   // i = c*16 + e
        int c = i >> 4, e = i & 15;
        mu_t[e * Cc + c] = g_sum[b * Cc * Ec + i] / g_cnt[b * Cc + c];
    }
    if (tid < Cc)
        rc[tid] = 1.0f / (g_cnt[b * Cc + tid] * (float)(Bc * Cc));
    __syncthreads();
    if (tid < Cc) {
        float nsq = 0.f;
        #pragma unroll
        for (int e = 0; e < Ec; ++e) {
            float m = mu_t[e * Cc + tid]; nsq += m * m;
        }
        mnorm[tid] = nsq;
    }
    __syncthreads();

    // x-norm chains (LDS-independent) and x.mu chains (LDS-dependent)
    float n0 = 0.f, n1 = 0.f, n2 = 0.f, n3 = 0.f;
    float p0 = 0.f, p1 = 0.f, p2 = 0.f, p3 = 0.f;

    // consume prefetched wave 0
    #pragma unroll
    for (int e = 0; e < 4; ++e) {
        const float* m = mu_t + e * Cc;
        n0 += v0[e].x * v0[e].x;  p0 += v0[e].x * m[l.x];
        n1 += v0[e].y * v0[e].y;  p1 += v0[e].y * m[l.y];
        n2 += v0[e].z * v0[e].z;  p2 += v0[e].z * m[l.z];
        n3 += v0[e].w * v0[e].w;  p3 += v0[e].w * m[l.w];
    }

    // waves 1..3: batch-load 4 LDG.128, then consume
    #pragma unroll
    for (int w = 1; w < 4; ++w) {
        float4 v[4];
        #pragma unroll
        for (int e = 0; e < 4; ++e)
            v[e] = *(const float4*)(base + (size_t)(w * 4 + e) * HWc);
        #pragma unroll
        for (int e = 0; e < 4; ++e) {
            const float* m = mu_t + (w * 4 + e) * Cc;
            n0 += v[e].x * v[e].x;  p0 += v[e].x * m[l.x];
            n1 += v[e].y * v[e].y;  p1 += v[e].y * m[l.y];
            n2 += v[e].z * v[e].z;  p2 += v[e].z * m[l.z];
            n3 += v[e].w * v[e].w;  p3 += v[e].w * m[l.w];
        }
    }

    float s0 = fmaxf(n0 - 2.f * p0 + mnorm[l.x], 0.f);
    float s1 = fmaxf(n1 - 2.f * p1 + mnorm[l.y], 0.f);
    float s2 = fmaxf(n2 - 2.f * p2 + mnorm[l.z], 0.f);
    float s3 = fmaxf(n3 - 2.f * p3 + mnorm[l.w], 0.f);

    float h0 = fmaxf(sqrtf(s0) - DELTA_VAR, 0.f);
    float h1 = fmaxf(sqrtf(s1) - DELTA_VAR, 0.f);
    float h2 = fmaxf(sqrtf(s2) - DELTA_VAR, 0.f);
    float h3 = fmaxf(sqrtf(s3) - DELTA_VAR, 0.f);

    float acc = ALPHA_W * (h0 * h0 * rc[l.x] + h1 * h1 * rc[l.y] +
                           h2 * h2 * rc[l.z] + h3 * h3 * rc[l.w]);

    // ---- block (0,0): distance + regularizer terms over all batches ----
    if (block00) {
        for (int i = tid; i < Bc * Cc * Ec; i += 256) {
            int bc = i >> 4;
            mu_all[i] = g_sum[i] / g_cnt[bc];
        }
        __syncthreads();

        // reg term: one entry per (b,c)
        for (int i = tid; i < Bc * Cc; i += 256) {
            float nsq = 0.f;
            #pragma unroll
            for (int e = 0; e < Ec; ++e) {
                float m = mu_all[i * 16 + e]; nsq += m * m;
            }
            float regc = (nsq == 0.f) ? 0.f : sqrtf(nsq);
            acc += GAMMA_W * regc * (1.0f / (Cc * Bc));
        }
        // distance term: all ordered pairs (ci != cj)
        for (int t = tid; t < Bc * Cc * Cc; t += 256) {
            int bb = t / (Cc * Cc);
            int rcidx = t - bb * (Cc * Cc);
            int ci = rcidx / Cc, cj = rcidx - ci * Cc;
            if (ci != cj) {
                const float* a = mu_all + (bb * Cc + ci) * 16;
                const float* c = mu_all + (bb * Cc + cj) * 16;
                float s = 0.f;
                #pragma unroll
                for (int e = 0; e < Ec; ++e) { float d = a[e] - c[e]; s += d * d; }
                float dist = (s == 0.f) ? 0.f : sqrtf(s);
                float hd = fmaxf(2.0f * DELTA_DIST - dist, 0.f);
                acc += BETA_W * hd * hd * (1.0f / ((float)Bc * Cc * (Cc - 1)));
            }
        }
    }

    // ---- block reduction -> single global atomic ----
    #pragma unroll
    for (int o = 16; o > 0; o >>= 1)
        acc += __shfl_down_sync(0xffffffffu, acc, o);
    if ((tid & 31) == 0) red[tid >> 5] = acc;
    __syncthreads();
    if (tid == 0) {
        float s = red[0];
        #pragma unroll
        for (int w = 1; w < 8; ++w) s += red[w];
        atomicAdd(out, s);
    }

    // ---- last-block election: reset scratch for next replay ----
    __syncthreads();
    __shared__ unsigned int s_last;
    if (tid == 0)
        s_last = (atomicAdd(&g_ticket, 1u) == (unsigned)(VAR_BLOCKS - 1));
    __syncthreads();
    if (s_last) {
        for (int i = tid; i < Bc * Cc * Ec; i += 256) g_sum[i] = 0.f;
        if (tid < Bc * Cc) g_cnt[tid] = 0.f;
        if (tid == 0) g_ticket = 0u;
    }
}

// ---------------- launch ----------------
extern "C" void kernel_launch(void* const* d_in, const int* in_sizes, int n_in,
                              void* d_out, int out_size) {
    const float* input  = (const float*)d_in[0];
    const int*   target = (const int*)d_in[1];
    float*       out    = (float*)d_out;

    dim3 g1(HWc / TILE, Bc);           // 128 x 4 = 512 blocks (one full wave)
    k_sums<<<g1, 256>>>(input, target, out);

    // k_var launched with Programmatic Dependent Launch: its blocks may start
    // (and run their input-only prologue) while k_sums is still executing;
    // cudaGridDependencySynchronize() inside orders the g_sum/g_cnt reads.
    cudaLaunchConfig_t cfg = {};
    cfg.gridDim  = dim3(VAR_GRID_X, Bc);   // 256 x 4 = 1024 blocks
    cfg.blockDim = dim3(256);
    cfg.dynamicSmemBytes = 0;
    cfg.stream = 0;                        // legacy default (capture) stream
    cudaLaunchAttribute attr[1];
    attr[0].id = cudaLaunchAttributeProgrammaticStreamSerialization;
    attr[0].val.programmaticStreamSerializationAllowed = 1;
    cfg.attrs = attr;
    cfg.numAttrs = 1;
    cudaLaunchKernelEx(&cfg, k_var, input, target, out);
}